// round 1
// baseline (speedup 1.0000x reference)
#include <cuda_runtime.h>
#include <cuda_bf16.h>

#define BATCH 8
#define H 512
#define W 512
#define KS 5
#define PAD 2

// Tile config for the fused kernel
#define TX 32
#define TY 8
#define SW (TX + 2*PAD)   // 36
#define SH (TY + 2*PAD)   // 12

__device__ float g_mn[BATCH];
__device__ float g_mx[BATCH];

// ---------------- Kernel A: per-batch min/max ----------------
__global__ void minmax_kernel(const float* __restrict__ cm) {
    const int b = blockIdx.x;
    const float4* p = reinterpret_cast<const float4*>(cm + (size_t)b * H * W);
    const int n4 = (H * W) / 4;

    float mn = 1e30f, mx = -1e30f;
    for (int i = threadIdx.x; i < n4; i += blockDim.x) {
        float4 v = p[i];
        mn = fminf(mn, fminf(fminf(v.x, v.y), fminf(v.z, v.w)));
        mx = fmaxf(mx, fmaxf(fmaxf(v.x, v.y), fmaxf(v.z, v.w)));
    }
    // warp reduce
    #pragma unroll
    for (int o = 16; o; o >>= 1) {
        mn = fminf(mn, __shfl_xor_sync(0xFFFFFFFFu, mn, o));
        mx = fmaxf(mx, __shfl_xor_sync(0xFFFFFFFFu, mx, o));
    }
    __shared__ float smn[32], smx[32];
    const int wid = threadIdx.x >> 5, lid = threadIdx.x & 31;
    if (lid == 0) { smn[wid] = mn; smx[wid] = mx; }
    __syncthreads();
    if (wid == 0) {
        const int nw = blockDim.x >> 5;
        mn = (lid < nw) ? smn[lid] : 1e30f;
        mx = (lid < nw) ? smx[lid] : -1e30f;
        #pragma unroll
        for (int o = 16; o; o >>= 1) {
            mn = fminf(mn, __shfl_xor_sync(0xFFFFFFFFu, mn, o));
            mx = fmaxf(mx, __shfl_xor_sync(0xFFFFFFFFu, mx, o));
        }
        if (lid == 0) { g_mn[b] = mn; g_mx[b] = mx; }
    }
}

// ---------------- Kernel B: fused normalize+conv+sample ----------------
__global__ __launch_bounds__(TX * TY) void sampler_kernel(
    const float* __restrict__ cm,
    const float* __restrict__ rnd,
    const float* __restrict__ kern,
    float* __restrict__ coords,   // [B,512,512,4,2]
    float* __restrict__ weights,  // [B,512,512,4]
    float* __restrict__ density)  // [B,1,512,512]
{
    __shared__ float tile[SH][SW];
    __shared__ float kw[KS * KS];

    const int b = blockIdx.z;
    const int tid = threadIdx.y * TX + threadIdx.x;

    if (tid < KS * KS) kw[tid] = kern[tid];

    const float mn = g_mn[b];
    const float mx = g_mx[b];
    const float rng = mx - mn;
    const float sc = (rng > 0.0f) ? (1.0f / rng) : 0.0f;

    const int x0 = blockIdx.x * TX - PAD;
    const int y0 = blockIdx.y * TY - PAD;
    const float* cmb = cm + (size_t)b * H * W;

    // Cooperative tile load of normalized values (zero halo == zero-padded conv)
    for (int i = tid; i < SH * SW; i += TX * TY) {
        const int ly = i / SW, lx = i - ly * SW;
        const int gy = y0 + ly, gx = x0 + lx;
        float v = 0.0f;
        if ((unsigned)gy < H && (unsigned)gx < W)
            v = (cmb[gy * W + gx] - mn) * sc;
        tile[ly][lx] = v;
    }
    __syncthreads();

    const int x = blockIdx.x * TX + threadIdx.x;
    const int y = blockIdx.y * TY + threadIdx.y;

    // 5x5 conv
    float acc = 0.0f;
    #pragma unroll
    for (int i = 0; i < KS; ++i)
        #pragma unroll
        for (int j = 0; j < KS; ++j)
            acc = fmaf(kw[i * KS + j], tile[threadIdx.y + i][threadIdx.x + j], acc);

    const float d = fmaf(0.9f, sqrtf(acc), 0.1f);   // MIN_D + (MAX_D-MIN_D)*sqrt

    // sample count
    const int ns = (d > 0.7f) ? 4 : ((d > 0.4f) ? 2 : 1);

    // base coords: linspace(-1,1,512) -> step 2/511
    const float step = 2.0f / 511.0f;
    const float by = fmaf((float)y, step, -1.0f);
    const float bx = fmaf((float)x, step, -1.0f);

    // offset scale: (2/512)*0.8, zeroed for single-sample pixels
    const float osc = (ns > 1) ? (2.0f / 512.0f * 0.8f) : 0.0f;

    const size_t pix = ((size_t)b * H + y) * W + x;
    const float4* r = reinterpret_cast<const float4*>(rnd + pix * 8);
    float4 r0 = r[0];
    float4 r1 = r[1];

    float4 c0, c1;
    c0.x = fmaf(r0.x - 0.5f, osc, by);
    c0.y = fmaf(r0.y - 0.5f, osc, bx);
    c0.z = fmaf(r0.z - 0.5f, osc, by);
    c0.w = fmaf(r0.w - 0.5f, osc, bx);
    c1.x = fmaf(r1.x - 0.5f, osc, by);
    c1.y = fmaf(r1.y - 0.5f, osc, bx);
    c1.z = fmaf(r1.z - 0.5f, osc, by);
    c1.w = fmaf(r1.w - 0.5f, osc, bx);

    float4* cout = reinterpret_cast<float4*>(coords + pix * 8);
    cout[0] = c0;
    cout[1] = c1;

    // weights: slot < ns ? d/ns : 0
    const float wv = d / (float)ns;
    float4 wq;
    wq.x = wv;
    wq.y = (ns > 1) ? wv : 0.0f;
    wq.z = (ns > 2) ? wv : 0.0f;
    wq.w = (ns > 2) ? wv : 0.0f;
    reinterpret_cast<float4*>(weights + pix * 4)[0] = wq;

    density[pix] = d;
}

extern "C" void kernel_launch(void* const* d_in, const int* in_sizes, int n_in,
                              void* d_out, int out_size) {
    const float* cm   = (const float*)d_in[0];  // [8,1,512,512]
    const float* rnd  = (const float*)d_in[1];  // [8,512,512,4,2]
    const float* kern = (const float*)d_in[2];  // [1,1,5,5]

    float* out = (float*)d_out;
    float* coords  = out;                                   // 8*512*512*4*2 = 16777216
    float* weights = out + (size_t)BATCH * H * W * 8;       // 8*512*512*4   =  8388608
    float* density = weights + (size_t)BATCH * H * W * 4;   // 8*512*512     =  2097152

    minmax_kernel<<<BATCH, 256>>>(cm);

    dim3 blk(TX, TY, 1);
    dim3 grd(W / TX, H / TY, BATCH);
    sampler_kernel<<<grd, blk>>>(cm, rnd, kern, coords, weights, density);
}

// round 2
// speedup vs baseline: 1.9992x; 1.9992x over previous
#include <cuda_runtime.h>
#include <cuda_bf16.h>

#define BATCH 8
#define H 512
#define W 512
#define KS 5
#define PAD 2

// Tile config for the fused kernel
#define TX 32
#define TY 8
#define SW (TX + 2*PAD)   // 36
#define SH (TY + 2*PAD)   // 12

#define CHUNKS 64         // phase-1 minmax blocks per batch

__device__ float g_pmn[BATCH * CHUNKS];
__device__ float g_pmx[BATCH * CHUNKS];

// ---------------- Kernel A: per-chunk partial min/max (full-chip) ----------------
__global__ __launch_bounds__(256) void minmax_partial_kernel(const float* __restrict__ cm) {
    const int b = blockIdx.y;
    const int c = blockIdx.x;
    // each block reduces 4096 floats = 1024 float4
    const float4* p = reinterpret_cast<const float4*>(cm) + ((size_t)b * (H * W / 4)) + (size_t)c * 1024;

    float mn = 1e30f, mx = -1e30f;
    #pragma unroll
    for (int i = 0; i < 4; ++i) {
        float4 v = p[threadIdx.x + i * 256];
        mn = fminf(mn, fminf(fminf(v.x, v.y), fminf(v.z, v.w)));
        mx = fmaxf(mx, fmaxf(fmaxf(v.x, v.y), fmaxf(v.z, v.w)));
    }
    #pragma unroll
    for (int o = 16; o; o >>= 1) {
        mn = fminf(mn, __shfl_xor_sync(0xFFFFFFFFu, mn, o));
        mx = fmaxf(mx, __shfl_xor_sync(0xFFFFFFFFu, mx, o));
    }
    __shared__ float smn[8], smx[8];
    const int wid = threadIdx.x >> 5, lid = threadIdx.x & 31;
    if (lid == 0) { smn[wid] = mn; smx[wid] = mx; }
    __syncthreads();
    if (threadIdx.x == 0) {
        #pragma unroll
        for (int i = 1; i < 8; ++i) { mn = fminf(mn, smn[i]); mx = fmaxf(mx, smx[i]); }
        g_pmn[b * CHUNKS + c] = mn;
        g_pmx[b * CHUNKS + c] = mx;
    }
}

// ---------------- Kernel B: fused reduce+normalize+conv+sample ----------------
__global__ __launch_bounds__(TX * TY) void sampler_kernel(
    const float* __restrict__ cm,
    const float* __restrict__ rnd,
    const float* __restrict__ kern,
    float* __restrict__ coords,   // [B,512,512,4,2]
    float* __restrict__ weights,  // [B,512,512,4]
    float* __restrict__ density)  // [B,1,512,512]
{
    __shared__ float tile[SH][SW];
    __shared__ float kw[KS * KS];
    __shared__ float red_mn[CHUNKS], red_mx[CHUNKS];
    __shared__ float s_mn, s_sc;

    const int b = blockIdx.z;
    const int tid = threadIdx.y * TX + threadIdx.x;

    // stage partials + kernel weights
    if (tid < CHUNKS) {
        red_mn[tid] = g_pmn[b * CHUNKS + tid];
        red_mx[tid] = g_pmx[b * CHUNKS + tid];
    } else if (tid < CHUNKS + KS * KS) {
        kw[tid - CHUNKS] = kern[tid - CHUNKS];
    }
    __syncthreads();

    // warp 0 reduces mn, warp 1 reduces mx
    if (tid < 64) {
        const int lid = tid & 31;
        if (tid < 32) {
            float v = fminf(red_mn[lid], red_mn[lid + 32]);
            #pragma unroll
            for (int o = 16; o; o >>= 1) v = fminf(v, __shfl_xor_sync(0xFFFFFFFFu, v, o));
            if (lid == 0) s_mn = v;
        } else {
            float v = fmaxf(red_mx[lid], red_mx[lid + 32]);
            #pragma unroll
            for (int o = 16; o; o >>= 1) v = fmaxf(v, __shfl_xor_sync(0xFFFFFFFFu, v, o));
            if (lid == 0) red_mx[0] = v;   // temp slot
        }
    }
    __syncthreads();
    if (tid == 0) {
        const float rng = red_mx[0] - s_mn;
        s_sc = (rng > 0.0f) ? (1.0f / rng) : 0.0f;
    }
    __syncthreads();

    const float mn = s_mn;
    const float sc = s_sc;

    const int x0 = blockIdx.x * TX - PAD;
    const int y0 = blockIdx.y * TY - PAD;
    const float* cmb = cm + (size_t)b * H * W;

    // Cooperative tile load of normalized values (zero halo == zero-padded conv)
    for (int i = tid; i < SH * SW; i += TX * TY) {
        const int ly = i / SW, lx = i - ly * SW;
        const int gy = y0 + ly, gx = x0 + lx;
        float v = 0.0f;
        if ((unsigned)gy < H && (unsigned)gx < W)
            v = (cmb[gy * W + gx] - mn) * sc;
        tile[ly][lx] = v;
    }
    __syncthreads();

    const int x = blockIdx.x * TX + threadIdx.x;
    const int y = blockIdx.y * TY + threadIdx.y;

    // 5x5 conv
    float acc = 0.0f;
    #pragma unroll
    for (int i = 0; i < KS; ++i)
        #pragma unroll
        for (int j = 0; j < KS; ++j)
            acc = fmaf(kw[i * KS + j], tile[threadIdx.y + i][threadIdx.x + j], acc);

    const float d = fmaf(0.9f, sqrtf(acc), 0.1f);   // MIN_D + (MAX_D-MIN_D)*sqrt

    // sample count
    const int ns = (d > 0.7f) ? 4 : ((d > 0.4f) ? 2 : 1);

    // base coords: linspace(-1,1,512) -> step 2/511
    const float step = 2.0f / 511.0f;
    const float by = fmaf((float)y, step, -1.0f);
    const float bx = fmaf((float)x, step, -1.0f);

    // offset scale: (2/512)*0.8, zeroed for single-sample pixels
    const float osc = (ns > 1) ? (2.0f / 512.0f * 0.8f) : 0.0f;

    const size_t pix = ((size_t)b * H + y) * W + x;
    const float4* r = reinterpret_cast<const float4*>(rnd + pix * 8);
    float4 r0 = __ldcs(r + 0);
    float4 r1 = __ldcs(r + 1);

    float4 c0, c1;
    c0.x = fmaf(r0.x - 0.5f, osc, by);
    c0.y = fmaf(r0.y - 0.5f, osc, bx);
    c0.z = fmaf(r0.z - 0.5f, osc, by);
    c0.w = fmaf(r0.w - 0.5f, osc, bx);
    c1.x = fmaf(r1.x - 0.5f, osc, by);
    c1.y = fmaf(r1.y - 0.5f, osc, bx);
    c1.z = fmaf(r1.z - 0.5f, osc, by);
    c1.w = fmaf(r1.w - 0.5f, osc, bx);

    float4* cout = reinterpret_cast<float4*>(coords + pix * 8);
    __stcs(cout + 0, c0);
    __stcs(cout + 1, c1);

    // weights: slot < ns ? d/ns : 0
    const float wv = d / (float)ns;
    float4 wq;
    wq.x = wv;
    wq.y = (ns > 1) ? wv : 0.0f;
    wq.z = (ns > 2) ? wv : 0.0f;
    wq.w = (ns > 2) ? wv : 0.0f;
    __stcs(reinterpret_cast<float4*>(weights + pix * 4), wq);

    __stcs(density + pix, d);
}

extern "C" void kernel_launch(void* const* d_in, const int* in_sizes, int n_in,
                              void* d_out, int out_size) {
    const float* cm   = (const float*)d_in[0];  // [8,1,512,512]
    const float* rnd  = (const float*)d_in[1];  // [8,512,512,4,2]
    const float* kern = (const float*)d_in[2];  // [1,1,5,5]

    float* out = (float*)d_out;
    float* coords  = out;                                   // 8*512*512*4*2 = 16777216
    float* weights = out + (size_t)BATCH * H * W * 8;       // 8*512*512*4   =  8388608
    float* density = weights + (size_t)BATCH * H * W * 4;   // 8*512*512     =  2097152

    dim3 agrd(CHUNKS, BATCH, 1);
    minmax_partial_kernel<<<agrd, 256>>>(cm);

    dim3 blk(TX, TY, 1);
    dim3 grd(W / TX, H / TY, BATCH);
    sampler_kernel<<<grd, blk>>>(cm, rnd, kern, coords, weights, density);
}